// round 16
// baseline (speedup 1.0000x reference)
#include <cuda_runtime.h>

// Problem constants
#define Nv    20000
#define Tt    32
#define Ee    640000
#define Cc    10
#define Kk    5
#define PADc  2
#define CAP   128      // bucket capacity per node, split in 2 x 64 sub-buckets
#define SEG   64       // sub-bucket capacity (mean seg deg 16; P(>=64) ~ e^-27)
#define MAXG  512
#define NTH   256
#define NUNITS 5000    // Nv/4 work units (4 nodes per warp; 1 node per 8-lane group)

// ---------------- static device scratch (no allocs allowed) ----------------
__device__ int   g_cnt[2][Nv];           // per-node per-segment cursors
__device__ int   g_adj[Nv * CAP];        // bucketed adjacency (2 segments/node)
__device__ float g_xn[Nv * Tt];          // normalized x of current layer
__device__ float g_cm[(Nv + 1) * Tt];    // per-node conv+max message (+zero row)
__device__ float g_x[Nv * Tt];           // layer-0 output
__device__ float g_stat0[64];            // layer-0 sum / sumsq per t
__device__ float g_stat1[64];            // layer-1 sum / sumsq per t
__device__ float g_out3[3];              // output partial sums
__device__ int   g_ctrA, g_ctrB;         // work-steal counters (aggr phases)

// -------- device-wide barrier: monotonic epoch, self-resetting arrive ------
__device__ unsigned g_bar_arrive;          // zero-init; reset by last arriver
__device__ volatile unsigned g_bar_epoch;  // monotonic across replays

__device__ __forceinline__ void gsync() {
    __syncthreads();
    if (threadIdx.x == 0) {
        __threadfence();
        unsigned e = g_bar_epoch;
        if (atomicAdd(&g_bar_arrive, 1u) == gridDim.x - 1u) {
            g_bar_arrive = 0u;
            __threadfence();
            g_bar_epoch = e + 1u;
        } else {
            while (g_bar_epoch == e) { __nanosleep(64); }
        }
        __threadfence();
    }
    __syncthreads();
}

// single-segment padded float4 gather, 8 edges per iteration: 8 lanes per
// node, lane covers t = sub*4 .. sub*4+3. 10 independent loads per step
// (2 int4 + 8 float4). Segment is 64-aligned so id loads are in-bounds;
// out-of-range edges pad to dummy row Nv (all zeros).
__device__ __forceinline__ void gather8(int deg, int base, int sub, float4& A, float4& B) {
    for (int k = 0; k < deg; k += 8) {
        int4 ia = *(const int4*)&g_adj[base + k];
        int4 ib = *(const int4*)&g_adj[base + k + 4];
        int a0 = (k + 0 < deg) ? ia.x : Nv;
        int a1 = (k + 1 < deg) ? ia.y : Nv;
        int a2 = (k + 2 < deg) ? ia.z : Nv;
        int a3 = (k + 3 < deg) ? ia.w : Nv;
        int a4 = (k + 4 < deg) ? ib.x : Nv;
        int a5 = (k + 5 < deg) ? ib.y : Nv;
        int a6 = (k + 6 < deg) ? ib.z : Nv;
        int a7 = (k + 7 < deg) ? ib.w : Nv;
        const float4 u0 = *(const float4*)&g_cm[a0 * Tt + sub * 4];
        const float4 u1 = *(const float4*)&g_cm[a1 * Tt + sub * 4];
        const float4 u2 = *(const float4*)&g_cm[a2 * Tt + sub * 4];
        const float4 u3 = *(const float4*)&g_cm[a3 * Tt + sub * 4];
        const float4 u4 = *(const float4*)&g_cm[a4 * Tt + sub * 4];
        const float4 u5 = *(const float4*)&g_cm[a5 * Tt + sub * 4];
        const float4 u6 = *(const float4*)&g_cm[a6 * Tt + sub * 4];
        const float4 u7 = *(const float4*)&g_cm[a7 * Tt + sub * 4];
        A.x += (u0.x + u1.x) + (u2.x + u3.x);
        A.y += (u0.y + u1.y) + (u2.y + u3.y);
        A.z += (u0.z + u1.z) + (u2.z + u3.z);
        A.w += (u0.w + u1.w) + (u2.w + u3.w);
        B.x += (u4.x + u5.x) + (u6.x + u7.x);
        B.y += (u4.y + u5.y) + (u6.y + u7.y);
        B.z += (u4.z + u5.z) + (u6.z + u7.z);
        B.w += (u4.w + u5.w) + (u6.w + u7.w);
    }
}

// both segments of one node -> neighbor sum for this lane's 4 t-values
__device__ __forceinline__ float4 gather_node(int d0, int d1, int base, int sub) {
    float4 A = make_float4(0.f, 0.f, 0.f, 0.f);
    float4 B = make_float4(0.f, 0.f, 0.f, 0.f);
    gather8(d0, base, sub, A, B);
    gather8(d1, base + SEG, sub, A, B);
    return make_float4(A.x + B.x, A.y + B.y, A.z + B.z, A.w + B.w);
}

// ---------------- the whole model as one persistent kernel ----------------
__global__ void __launch_bounds__(NTH, 4) sage_fused(
    const float* __restrict__ x,     // [N,T]
    const float* __restrict__ convW, // [L,C,1,K]
    const float* __restrict__ convb, // [L,C]
    const float* __restrict__ alpha, // [L,T]
    const float* __restrict__ scale, // [L,T]
    const float* __restrict__ shift, // [L,T]
    const float* __restrict__ Wout,  // [3,N]
    const float* __restrict__ bout,  // [3]
    const int*   __restrict__ ei,    // [2,E]
    float*       __restrict__ out)   // [3]
{
    const int tid  = threadIdx.x;
    const int lane = tid & 31;
    const int w    = tid >> 5;
    const int sub  = lane & 7;   // position within 8-lane node group
    const int grp  = lane >> 3;  // node group 0..3 within warp
    const int b    = blockIdx.x;
    const int G    = gridDim.x;
    const int nthreads = G * NTH;
    const int gtid     = b * NTH + tid;
    const int nwarps   = G * 8;
    const int gwarp    = b * 8 + w;

    __shared__ float sh[8][64];
    __shared__ float sm[Tt], smul[Tt], ssh[Tt];
    __shared__ float sW[Cc * Kk];
    __shared__ float sbias[Cc];
    __shared__ float shp[8][3];

    // ---- P0: zero segment cursors + accumulators + counters + dummy row ----
    for (int i = gtid; i < 2 * Nv; i += nthreads) ((int*)g_cnt)[i] = 0;
    if (b == 0) {
        if (tid < 64) { g_stat0[tid] = 0.f; g_stat1[tid] = 0.f; }
        if (tid < 3)  g_out3[tid] = 0.f;
        if (tid < Tt) g_cm[Nv * Tt + tid] = 0.f;  // zero padding row
        if (tid == 0) { g_ctrA = 0; g_ctrB = 0; }
    }
    gsync();  // S1

    // ---- P1: single-pass 2-segment adjacency build + layer-0 column stats ----
    {
        const int r = lane & 1;  // segment parity: halves per-address contention
        for (int e = gtid; e < Ee; e += nthreads * 4) {
            int ss[4], dd[4];
#pragma unroll
            for (int k = 0; k < 4; k++) {
                int idx = e + k * nthreads;
                if (idx < Ee) { ss[k] = ei[idx]; dd[k] = ei[Ee + idx]; }
                else          { dd[k] = -1; }
            }
#pragma unroll
            for (int k = 0; k < 4; k++) {
                if (dd[k] >= 0) {
                    int slot = atomicAdd(&g_cnt[r][dd[k]], 1);
                    if (slot < SEG) g_adj[dd[k] * CAP + r * SEG + slot] = ss[k];
                }
            }
        }
    }
    {
        const int GSB = (G < 128) ? G : 128;
        if (b < GSB) {
            float s = 0.f, q = 0.f;
            for (int n = b * 8 + w; n < Nv; n += GSB * 8) {
                float v = x[n * Tt + lane];
                s += v; q = fmaf(v, v, q);
            }
            sh[w][lane] = s; sh[w][32 + lane] = q;
            __syncthreads();
            if (tid < 64) {
                float v = 0.f;
#pragma unroll
                for (int i = 0; i < 8; i++) v += sh[i][tid];
                atomicAdd(&g_stat0[tid], v);
            }
        }
    }
    gsync();  // S2

    // ---- P2: layer-0 stats finish (per block) + normconv-0 ----
    if (tid < Tt) {
        float s = g_stat0[tid], q = g_stat0[32 + tid];
        float m = s / (float)Nv;
        float a = alpha[tid];
        float nsq = q + (float)Nv * m * m * (a * a - 2.f * a);
        float invn = sqrtf((float)Nv) * rsqrtf(nsq);
        sm[tid]   = a * m;
        smul[tid] = invn * scale[tid];
        ssh[tid]  = shift[tid];
    }
    if (tid < Cc * Kk) sW[tid] = convW[tid];
    if (tid < Cc)      sbias[tid] = convb[tid];
    __syncthreads();
    for (int node = gwarp; node < Nv; node += nwarps) {
        float v = x[node * Tt + lane];
        v = fmaf(v - sm[lane], smul[lane], ssh[lane]);
        g_xn[node * Tt + lane] = v;
        float win[Kk];
#pragma unroll
        for (int d = -PADc; d <= PADc; d++) {
            int si = lane + d;
            float u = __shfl_sync(0xffffffffu, v, si & 31);
            win[d + PADc] = (si >= 0 && si < Tt) ? u : 0.f;
        }
        float mx = -3.0e38f;
#pragma unroll
        for (int c = 0; c < Cc; c++) {
            float a2 = sbias[c];
#pragma unroll
            for (int k = 0; k < Kk; k++) a2 = fmaf(win[k], sW[c * Kk + k], a2);
            mx = fmaxf(mx, a2);
        }
        g_cm[node * Tt + lane] = mx;
    }
    gsync();  // S3

    // ---- P3: aggr-0 (+relu) -> g_x, fused layer-1 stats (work-stealing) ----
    {
        float4 s4 = make_float4(0.f, 0.f, 0.f, 0.f);
        float4 q4 = make_float4(0.f, 0.f, 0.f, 0.f);
        for (;;) {
            int nb;
            if (lane == 0) nb = atomicAdd(&g_ctrA, 1);
            nb = __shfl_sync(0xffffffffu, nb, 0);
            if (nb >= NUNITS) break;
            const int node = nb * 4 + grp;
            int d0 = g_cnt[0][node]; if (d0 > SEG) d0 = SEG;
            int d1 = g_cnt[1][node]; if (d1 > SEG) d1 = SEG;
            float4 acc = gather_node(d0, d1, node * CAP, sub);
            const int deg = d0 + d1;
            const float inv = 1.0f / (float)(deg > 1 ? deg : 1);
            const float4 xn = *(const float4*)&g_xn[node * Tt + sub * 4];
            float4 v;
            v.x = fmaxf(0.5f * fmaf(acc.x, inv, xn.x), 0.f);
            v.y = fmaxf(0.5f * fmaf(acc.y, inv, xn.y), 0.f);
            v.z = fmaxf(0.5f * fmaf(acc.z, inv, xn.z), 0.f);
            v.w = fmaxf(0.5f * fmaf(acc.w, inv, xn.w), 0.f);
            *(float4*)&g_x[node * Tt + sub * 4] = v;
            s4.x += v.x; q4.x = fmaf(v.x, v.x, q4.x);
            s4.y += v.y; q4.y = fmaf(v.y, v.y, q4.y);
            s4.z += v.z; q4.z = fmaf(v.z, v.z, q4.z);
            s4.w += v.w; q4.w = fmaf(v.w, v.w, q4.w);
        }
        // reduce across the 4 groups (lanes with equal sub share t-range)
#pragma unroll
        for (int off = 8; off < 32; off <<= 1) {
            s4.x += __shfl_xor_sync(0xffffffffu, s4.x, off);
            s4.y += __shfl_xor_sync(0xffffffffu, s4.y, off);
            s4.z += __shfl_xor_sync(0xffffffffu, s4.z, off);
            s4.w += __shfl_xor_sync(0xffffffffu, s4.w, off);
            q4.x += __shfl_xor_sync(0xffffffffu, q4.x, off);
            q4.y += __shfl_xor_sync(0xffffffffu, q4.y, off);
            q4.z += __shfl_xor_sync(0xffffffffu, q4.z, off);
            q4.w += __shfl_xor_sync(0xffffffffu, q4.w, off);
        }
        if (lane < 8) {
            sh[w][lane * 4 + 0] = s4.x;  sh[w][32 + lane * 4 + 0] = q4.x;
            sh[w][lane * 4 + 1] = s4.y;  sh[w][32 + lane * 4 + 1] = q4.y;
            sh[w][lane * 4 + 2] = s4.z;  sh[w][32 + lane * 4 + 2] = q4.z;
            sh[w][lane * 4 + 3] = s4.w;  sh[w][32 + lane * 4 + 3] = q4.w;
        }
        __syncthreads();
        if (tid < 64) {
            float v = 0.f;
#pragma unroll
            for (int i = 0; i < 8; i++) v += sh[i][tid];
            atomicAdd(&g_stat1[tid], v);
        }
    }
    gsync();  // S4

    // ---- P4: layer-1 stats finish + normconv-1 (src = g_x) ----
    if (tid < Tt) {
        float s = g_stat1[tid], q = g_stat1[32 + tid];
        float m = s / (float)Nv;
        float a = alpha[Tt + tid];
        float nsq = q + (float)Nv * m * m * (a * a - 2.f * a);
        float invn = sqrtf((float)Nv) * rsqrtf(nsq);
        sm[tid]   = a * m;
        smul[tid] = invn * scale[Tt + tid];
        ssh[tid]  = shift[Tt + tid];
    }
    if (tid < Cc * Kk) sW[tid] = convW[Cc * Kk + tid];
    if (tid < Cc)      sbias[tid] = convb[Cc + tid];
    __syncthreads();
    for (int node = gwarp; node < Nv; node += nwarps) {
        float v = g_x[node * Tt + lane];
        v = fmaf(v - sm[lane], smul[lane], ssh[lane]);
        g_xn[node * Tt + lane] = v;
        float win[Kk];
#pragma unroll
        for (int d = -PADc; d <= PADc; d++) {
            int si = lane + d;
            float u = __shfl_sync(0xffffffffu, v, si & 31);
            win[d + PADc] = (si >= 0 && si < Tt) ? u : 0.f;
        }
        float mx = -3.0e38f;
#pragma unroll
        for (int c = 0; c < Cc; c++) {
            float a2 = sbias[c];
#pragma unroll
            for (int k = 0; k < Kk; k++) a2 = fmaf(win[k], sW[c * Kk + k], a2);
            mx = fmaxf(mx, a2);
        }
        g_cm[node * Tt + lane] = mx;
    }
    gsync();  // S5

    // ---- P5: aggr-1 (+relu) + output head partials (work-stealing) ----
    {
        float p0 = 0.f, p1 = 0.f, p2 = 0.f;
        for (;;) {
            int nb;
            if (lane == 0) nb = atomicAdd(&g_ctrB, 1);
            nb = __shfl_sync(0xffffffffu, nb, 0);
            if (nb >= NUNITS) break;
            const int node = nb * 4 + grp;
            int d0 = g_cnt[0][node]; if (d0 > SEG) d0 = SEG;
            int d1 = g_cnt[1][node]; if (d1 > SEG) d1 = SEG;
            float4 acc = gather_node(d0, d1, node * CAP, sub);
            const int deg = d0 + d1;
            const float inv = 1.0f / (float)(deg > 1 ? deg : 1);
            const float4 xn = *(const float4*)&g_xn[node * Tt + sub * 4];
            float rs = fmaxf(0.5f * fmaf(acc.x, inv, xn.x), 0.f)
                     + fmaxf(0.5f * fmaf(acc.y, inv, xn.y), 0.f)
                     + fmaxf(0.5f * fmaf(acc.z, inv, xn.z), 0.f)
                     + fmaxf(0.5f * fmaf(acc.w, inv, xn.w), 0.f);
            // rowsum within the 8-lane group
            rs += __shfl_xor_sync(0xffffffffu, rs, 1);
            rs += __shfl_xor_sync(0xffffffffu, rs, 2);
            rs += __shfl_xor_sync(0xffffffffu, rs, 4);
            if (sub == 0) {
                p0 = fmaf(Wout[node], rs, p0);
                p1 = fmaf(Wout[Nv + node], rs, p1);
                p2 = fmaf(Wout[2 * Nv + node], rs, p2);
            }
        }
        // sum the 4 group-leader lanes (others hold 0)
#pragma unroll
        for (int off = 8; off < 32; off <<= 1) {
            p0 += __shfl_xor_sync(0xffffffffu, p0, off);
            p1 += __shfl_xor_sync(0xffffffffu, p1, off);
            p2 += __shfl_xor_sync(0xffffffffu, p2, off);
        }
        if (lane == 0) { shp[w][0] = p0; shp[w][1] = p1; shp[w][2] = p2; }
        __syncthreads();
        if (tid < 3) {
            float v = 0.f;
#pragma unroll
            for (int i = 0; i < 8; i++) v += shp[i][tid];
            atomicAdd(&g_out3[tid], v);
        }
    }
    gsync();  // S6

    // ---- P6: write the 3 logits ----
    if (b == 0 && tid < 3) out[tid] = g_out3[tid] + bout[tid];
}

// ---------------- launch ---------------------------------------------------
extern "C" void kernel_launch(void* const* d_in, const int* in_sizes, int n_in,
                              void* d_out, int out_size) {
    const float* x     = (const float*)d_in[0];
    const float* convW = (const float*)d_in[1];
    const float* convb = (const float*)d_in[2];
    const float* alpha = (const float*)d_in[3];
    const float* scale = (const float*)d_in[4];
    const float* shift = (const float*)d_in[5];
    const float* Wout  = (const float*)d_in[6];
    const float* bout  = (const float*)d_in[7];
    const int*   ei    = (const int*)d_in[8];
    float*       out   = (float*)d_out;

    int dev = 0;
    cudaGetDevice(&dev);
    int sms = 0;
    cudaDeviceGetAttribute(&sms, cudaDevAttrMultiProcessorCount, dev);
    int bpm = 0;
    cudaOccupancyMaxActiveBlocksPerMultiprocessor(&bpm, sage_fused, NTH, 0);
    if (bpm < 1) bpm = 1;
    int G = sms * bpm;
    if (G > MAXG) G = MAXG;

    void* args[10] = {
        (void*)&x, (void*)&convW, (void*)&convb, (void*)&alpha, (void*)&scale,
        (void*)&shift, (void*)&Wout, (void*)&bout, (void*)&ei, (void*)&out
    };
    cudaLaunchCooperativeKernel((const void*)sage_fused, dim3(G), dim3(NTH),
                                args, 0, (cudaStream_t)0);
}

// round 17
// speedup vs baseline: 1.0375x; 1.0375x over previous
#include <cuda_runtime.h>

// Problem constants
#define Nv    20000
#define Tt    32
#define Ee    640000
#define Cc    10
#define Kk    5
#define PADc  2
#define CAP   128      // bucket capacity per node (mean deg 32; P(>=128) ~ e^-81)
#define MAXG  512
#define NTH   256
#define NUNITS 5000    // Nv/4 work units (4 nodes per warp per unit; 1 node per 8-lane group)

// ---------------- static device scratch (no allocs allowed) ----------------
__device__ int   g_cnt[Nv];              // per-node degree / bucket cursor
__device__ int   g_adj[Nv * CAP];        // bucketed adjacency (src per dst)
__device__ float g_xn[Nv * Tt];          // normalized x of current layer
__device__ float g_cm[(Nv + 1) * Tt];    // per-node conv+max message (+zero row)
__device__ float g_x[Nv * Tt];           // layer-0 output
__device__ float g_stat0[64];            // layer-0 sum / sumsq per t
__device__ float g_stat1[64];            // layer-1 sum / sumsq per t
__device__ float g_out3[3];              // output partial sums
__device__ int   g_ctrA, g_ctrB;         // work-steal counters (aggr phases)

// -------- device-wide barrier: monotonic epoch, self-resetting arrive ------
__device__ unsigned g_bar_arrive;          // zero-init; reset by last arriver
__device__ volatile unsigned g_bar_epoch;  // monotonic across replays

__device__ __forceinline__ void gsync() {
    __syncthreads();
    if (threadIdx.x == 0) {
        __threadfence();
        unsigned e = g_bar_epoch;
        if (atomicAdd(&g_bar_arrive, 1u) == gridDim.x - 1u) {
            g_bar_arrive = 0u;
            __threadfence();
            g_bar_epoch = e + 1u;
        } else {
            while (g_bar_epoch == e) { __nanosleep(64); }
        }
        __threadfence();
    }
    __syncthreads();
}

// single-node padded float4 gather, 8 edges per iteration: 8 lanes per node,
// lane covers t = sub*4 .. sub*4+3. 10 independent loads per step (2 int4 +
// 8 float4). Bucket is CAP-aligned (CAP % 8 == 0) so id loads are always
// in-bounds; out-of-range edges pad to dummy row Nv (all zeros).
__device__ __forceinline__ float4 gather8(int deg, int base, int sub) {
    float4 A = make_float4(0.f, 0.f, 0.f, 0.f);
    float4 B = make_float4(0.f, 0.f, 0.f, 0.f);
    for (int k = 0; k < deg; k += 8) {
        int4 ia = *(const int4*)&g_adj[base + k];
        int4 ib = *(const int4*)&g_adj[base + k + 4];
        int a0 = (k + 0 < deg) ? ia.x : Nv;
        int a1 = (k + 1 < deg) ? ia.y : Nv;
        int a2 = (k + 2 < deg) ? ia.z : Nv;
        int a3 = (k + 3 < deg) ? ia.w : Nv;
        int a4 = (k + 4 < deg) ? ib.x : Nv;
        int a5 = (k + 5 < deg) ? ib.y : Nv;
        int a6 = (k + 6 < deg) ? ib.z : Nv;
        int a7 = (k + 7 < deg) ? ib.w : Nv;
        const float4 u0 = *(const float4*)&g_cm[a0 * Tt + sub * 4];
        const float4 u1 = *(const float4*)&g_cm[a1 * Tt + sub * 4];
        const float4 u2 = *(const float4*)&g_cm[a2 * Tt + sub * 4];
        const float4 u3 = *(const float4*)&g_cm[a3 * Tt + sub * 4];
        const float4 u4 = *(const float4*)&g_cm[a4 * Tt + sub * 4];
        const float4 u5 = *(const float4*)&g_cm[a5 * Tt + sub * 4];
        const float4 u6 = *(const float4*)&g_cm[a6 * Tt + sub * 4];
        const float4 u7 = *(const float4*)&g_cm[a7 * Tt + sub * 4];
        A.x += (u0.x + u1.x) + (u2.x + u3.x);
        A.y += (u0.y + u1.y) + (u2.y + u3.y);
        A.z += (u0.z + u1.z) + (u2.z + u3.z);
        A.w += (u0.w + u1.w) + (u2.w + u3.w);
        B.x += (u4.x + u5.x) + (u6.x + u7.x);
        B.y += (u4.y + u5.y) + (u6.y + u7.y);
        B.z += (u4.z + u5.z) + (u6.z + u7.z);
        B.w += (u4.w + u5.w) + (u6.w + u7.w);
    }
    return make_float4(A.x + B.x, A.y + B.y, A.z + B.z, A.w + B.w);
}

// ---------------- the whole model as one persistent kernel ----------------
__global__ void __launch_bounds__(NTH, 4) sage_fused(
    const float* __restrict__ x,     // [N,T]
    const float* __restrict__ convW, // [L,C,1,K]
    const float* __restrict__ convb, // [L,C]
    const float* __restrict__ alpha, // [L,T]
    const float* __restrict__ scale, // [L,T]
    const float* __restrict__ shift, // [L,T]
    const float* __restrict__ Wout,  // [3,N]
    const float* __restrict__ bout,  // [3]
    const int*   __restrict__ ei,    // [2,E]
    float*       __restrict__ out)   // [3]
{
    const int tid  = threadIdx.x;
    const int lane = tid & 31;
    const int w    = tid >> 5;
    const int sub  = lane & 7;   // position within 8-lane node group
    const int grp  = lane >> 3;  // node group 0..3 within warp
    const int b    = blockIdx.x;
    const int G    = gridDim.x;
    const int nthreads = G * NTH;
    const int gtid     = b * NTH + tid;
    const int nwarps   = G * 8;
    const int gwarp    = b * 8 + w;

    __shared__ float sh[8][64];
    __shared__ float sm[Tt], smul[Tt], ssh[Tt];
    __shared__ float sW[Cc * Kk];
    __shared__ float sbias[Cc];
    __shared__ float shp[8][3];

    // ---- P0: zero bucket cursors + accumulators + counters + dummy row ----
    for (int i = gtid; i < Nv; i += nthreads) g_cnt[i] = 0;
    if (b == 0) {
        if (tid < 64) { g_stat0[tid] = 0.f; g_stat1[tid] = 0.f; }
        if (tid < 3)  g_out3[tid] = 0.f;
        if (tid < Tt) g_cm[Nv * Tt + tid] = 0.f;  // zero padding row
        if (tid == 0) { g_ctrA = 0; g_ctrB = 0; }
    }
    gsync();  // S1

    // ---- P1: single-pass bucketed adjacency build + layer-0 column stats ----
    for (int e = gtid; e < Ee; e += nthreads * 4) {
        int ss[4], dd[4];
#pragma unroll
        for (int k = 0; k < 4; k++) {
            int idx = e + k * nthreads;
            if (idx < Ee) { ss[k] = ei[idx]; dd[k] = ei[Ee + idx]; }
            else          { dd[k] = -1; }
        }
#pragma unroll
        for (int k = 0; k < 4; k++) {
            if (dd[k] >= 0) {
                int slot = atomicAdd(&g_cnt[dd[k]], 1);
                if (slot < CAP) g_adj[dd[k] * CAP + slot] = ss[k];
            }
        }
    }
    {
        // layer-0 column stats over ALL blocks (was 128 of 512: 384 blocks
        // idled at S2 while 128 streamed 2.56 MB; now the tail is 4x shorter)
        float s = 0.f, q = 0.f;
        for (int n = gwarp; n < Nv; n += nwarps) {
            float v = x[n * Tt + lane];
            s += v; q = fmaf(v, v, q);
        }
        sh[w][lane] = s; sh[w][32 + lane] = q;
        __syncthreads();
        if (tid < 64) {
            float v = 0.f;
#pragma unroll
            for (int i = 0; i < 8; i++) v += sh[i][tid];
            atomicAdd(&g_stat0[tid], v);
        }
    }
    gsync();  // S2

    // ---- P2: layer-0 stats finish (per block) + normconv-0 ----
    if (tid < Tt) {
        float s = g_stat0[tid], q = g_stat0[32 + tid];
        float m = s / (float)Nv;
        float a = alpha[tid];
        float nsq = q + (float)Nv * m * m * (a * a - 2.f * a);
        float invn = sqrtf((float)Nv) * rsqrtf(nsq);
        sm[tid]   = a * m;
        smul[tid] = invn * scale[tid];
        ssh[tid]  = shift[tid];
    }
    if (tid < Cc * Kk) sW[tid] = convW[tid];
    if (tid < Cc)      sbias[tid] = convb[tid];
    __syncthreads();
    for (int node = gwarp; node < Nv; node += nwarps) {
        float v = x[node * Tt + lane];
        v = fmaf(v - sm[lane], smul[lane], ssh[lane]);
        g_xn[node * Tt + lane] = v;
        float win[Kk];
#pragma unroll
        for (int d = -PADc; d <= PADc; d++) {
            int si = lane + d;
            float u = __shfl_sync(0xffffffffu, v, si & 31);
            win[d + PADc] = (si >= 0 && si < Tt) ? u : 0.f;
        }
        float mx = -3.0e38f;
#pragma unroll
        for (int c = 0; c < Cc; c++) {
            float a2 = sbias[c];
#pragma unroll
            for (int k = 0; k < Kk; k++) a2 = fmaf(win[k], sW[c * Kk + k], a2);
            mx = fmaxf(mx, a2);
        }
        g_cm[node * Tt + lane] = mx;
    }
    gsync();  // S3

    // ---- P3: aggr-0 (+relu) -> g_x, fused layer-1 stats (work-stealing) ----
    {
        float4 s4 = make_float4(0.f, 0.f, 0.f, 0.f);
        float4 q4 = make_float4(0.f, 0.f, 0.f, 0.f);
        for (;;) {
            int nb;
            if (lane == 0) nb = atomicAdd(&g_ctrA, 1);
            nb = __shfl_sync(0xffffffffu, nb, 0);
            if (nb >= NUNITS) break;
            const int node = nb * 4 + grp;
            int deg = g_cnt[node];
            if (deg > CAP) deg = CAP;
            float4 acc = gather8(deg, node * CAP, sub);
            const float inv = 1.0f / (float)(deg > 1 ? deg : 1);
            const float4 xn = *(const float4*)&g_xn[node * Tt + sub * 4];
            float4 v;
            v.x = fmaxf(0.5f * fmaf(acc.x, inv, xn.x), 0.f);
            v.y = fmaxf(0.5f * fmaf(acc.y, inv, xn.y), 0.f);
            v.z = fmaxf(0.5f * fmaf(acc.z, inv, xn.z), 0.f);
            v.w = fmaxf(0.5f * fmaf(acc.w, inv, xn.w), 0.f);
            *(float4*)&g_x[node * Tt + sub * 4] = v;
            s4.x += v.x; q4.x = fmaf(v.x, v.x, q4.x);
            s4.y += v.y; q4.y = fmaf(v.y, v.y, q4.y);
            s4.z += v.z; q4.z = fmaf(v.z, v.z, q4.z);
            s4.w += v.w; q4.w = fmaf(v.w, v.w, q4.w);
        }
        // reduce across the 4 groups (lanes with equal sub share t-range)
#pragma unroll
        for (int off = 8; off < 32; off <<= 1) {
            s4.x += __shfl_xor_sync(0xffffffffu, s4.x, off);
            s4.y += __shfl_xor_sync(0xffffffffu, s4.y, off);
            s4.z += __shfl_xor_sync(0xffffffffu, s4.z, off);
            s4.w += __shfl_xor_sync(0xffffffffu, s4.w, off);
            q4.x += __shfl_xor_sync(0xffffffffu, q4.x, off);
            q4.y += __shfl_xor_sync(0xffffffffu, q4.y, off);
            q4.z += __shfl_xor_sync(0xffffffffu, q4.z, off);
            q4.w += __shfl_xor_sync(0xffffffffu, q4.w, off);
        }
        if (lane < 8) {
            sh[w][lane * 4 + 0] = s4.x;  sh[w][32 + lane * 4 + 0] = q4.x;
            sh[w][lane * 4 + 1] = s4.y;  sh[w][32 + lane * 4 + 1] = q4.y;
            sh[w][lane * 4 + 2] = s4.z;  sh[w][32 + lane * 4 + 2] = q4.z;
            sh[w][lane * 4 + 3] = s4.w;  sh[w][32 + lane * 4 + 3] = q4.w;
        }
        __syncthreads();
        if (tid < 64) {
            float v = 0.f;
#pragma unroll
            for (int i = 0; i < 8; i++) v += sh[i][tid];
            atomicAdd(&g_stat1[tid], v);
        }
    }
    gsync();  // S4

    // ---- P4: layer-1 stats finish + normconv-1 (src = g_x) ----
    if (tid < Tt) {
        float s = g_stat1[tid], q = g_stat1[32 + tid];
        float m = s / (float)Nv;
        float a = alpha[Tt + tid];
        float nsq = q + (float)Nv * m * m * (a * a - 2.f * a);
        float invn = sqrtf((float)Nv) * rsqrtf(nsq);
        sm[tid]   = a * m;
        smul[tid] = invn * scale[Tt + tid];
        ssh[tid]  = shift[Tt + tid];
    }
    if (tid < Cc * Kk) sW[tid] = convW[Cc * Kk + tid];
    if (tid < Cc)      sbias[tid] = convb[Cc + tid];
    __syncthreads();
    for (int node = gwarp; node < Nv; node += nwarps) {
        float v = g_x[node * Tt + lane];
        v = fmaf(v - sm[lane], smul[lane], ssh[lane]);
        g_xn[node * Tt + lane] = v;
        float win[Kk];
#pragma unroll
        for (int d = -PADc; d <= PADc; d++) {
            int si = lane + d;
            float u = __shfl_sync(0xffffffffu, v, si & 31);
            win[d + PADc] = (si >= 0 && si < Tt) ? u : 0.f;
        }
        float mx = -3.0e38f;
#pragma unroll
        for (int c = 0; c < Cc; c++) {
            float a2 = sbias[c];
#pragma unroll
            for (int k = 0; k < Kk; k++) a2 = fmaf(win[k], sW[c * Kk + k], a2);
            mx = fmaxf(mx, a2);
        }
        g_cm[node * Tt + lane] = mx;
    }
    gsync();  // S5

    // ---- P5: aggr-1 (+relu) + output head partials (work-stealing) ----
    {
        float p0 = 0.f, p1 = 0.f, p2 = 0.f;
        for (;;) {
            int nb;
            if (lane == 0) nb = atomicAdd(&g_ctrB, 1);
            nb = __shfl_sync(0xffffffffu, nb, 0);
            if (nb >= NUNITS) break;
            const int node = nb * 4 + grp;
            int deg = g_cnt[node];
            if (deg > CAP) deg = CAP;
            float4 acc = gather8(deg, node * CAP, sub);
            const float inv = 1.0f / (float)(deg > 1 ? deg : 1);
            const float4 xn = *(const float4*)&g_xn[node * Tt + sub * 4];
            float rs = fmaxf(0.5f * fmaf(acc.x, inv, xn.x), 0.f)
                     + fmaxf(0.5f * fmaf(acc.y, inv, xn.y), 0.f)
                     + fmaxf(0.5f * fmaf(acc.z, inv, xn.z), 0.f)
                     + fmaxf(0.5f * fmaf(acc.w, inv, xn.w), 0.f);
            // rowsum within the 8-lane group
            rs += __shfl_xor_sync(0xffffffffu, rs, 1);
            rs += __shfl_xor_sync(0xffffffffu, rs, 2);
            rs += __shfl_xor_sync(0xffffffffu, rs, 4);
            if (sub == 0) {
                p0 = fmaf(Wout[node], rs, p0);
                p1 = fmaf(Wout[Nv + node], rs, p1);
                p2 = fmaf(Wout[2 * Nv + node], rs, p2);
            }
        }
        // sum the 4 group-leader lanes (others hold 0)
#pragma unroll
        for (int off = 8; off < 32; off <<= 1) {
            p0 += __shfl_xor_sync(0xffffffffu, p0, off);
            p1 += __shfl_xor_sync(0xffffffffu, p1, off);
            p2 += __shfl_xor_sync(0xffffffffu, p2, off);
        }
        if (lane == 0) { shp[w][0] = p0; shp[w][1] = p1; shp[w][2] = p2; }
        __syncthreads();
        if (tid < 3) {
            float v = 0.f;
#pragma unroll
            for (int i = 0; i < 8; i++) v += shp[i][tid];
            atomicAdd(&g_out3[tid], v);
        }
    }
    gsync();  // S6

    // ---- P6: write the 3 logits ----
    if (b == 0 && tid < 3) out[tid] = g_out3[tid] + bout[tid];
}

// ---------------- launch ---------------------------------------------------
extern "C" void kernel_launch(void* const* d_in, const int* in_sizes, int n_in,
                              void* d_out, int out_size) {
    const float* x     = (const float*)d_in[0];
    const float* convW = (const float*)d_in[1];
    const float* convb = (const float*)d_in[2];
    const float* alpha = (const float*)d_in[3];
    const float* scale = (const float*)d_in[4];
    const float* shift = (const float*)d_in[5];
    const float* Wout  = (const float*)d_in[6];
    const float* bout  = (const float*)d_in[7];
    const int*   ei    = (const int*)d_in[8];
    float*       out   = (float*)d_out;

    int dev = 0;
    cudaGetDevice(&dev);
    int sms = 0;
    cudaDeviceGetAttribute(&sms, cudaDevAttrMultiProcessorCount, dev);
    int bpm = 0;
    cudaOccupancyMaxActiveBlocksPerMultiprocessor(&bpm, sage_fused, NTH, 0);
    if (bpm < 1) bpm = 1;
    int G = sms * bpm;
    if (G > MAXG) G = MAXG;

    void* args[10] = {
        (void*)&x, (void*)&convW, (void*)&convb, (void*)&alpha, (void*)&scale,
        (void*)&shift, (void*)&Wout, (void*)&bout, (void*)&ei, (void*)&out
    };
    cudaLaunchCooperativeKernel((const void*)sage_fused, dim3(G), dim3(NTH),
                                args, 0, (cudaStream_t)0);
}